// round 11
// baseline (speedup 1.0000x reference)
#include <cuda_runtime.h>
#include <cstdint>

typedef unsigned long long ull;

#define NB 2
#define NN 8192
#define NI 32
#define NE 128
#define NP (NB*NN)      // 16384 points
#define NBI (NB*NI)     // 64 (b,i) rows
#define NWORDS (NN/32)  // 256 mask words per (b,i)

// ---------------- device scratch ----------------
__device__ float    g_U[(size_t)NP*64];    // U = h @ Wd64  (4 MB)
__device__ float    g_Wd64[64*64];         // Wd1 @ W2eff   [k][o]
__device__ float    g_pe[NBI*NE];          // pos_embed
__device__ float    g_V1[NBI*64];          // pe@Wd1^T + bd1
__device__ float    g_V2[NBI*64];          // (pe-ne)@Wd1^T + bd1
__device__ unsigned g_mask[NBI*NWORDS];    // initial mask bitmaps

// ---------------- packed f32x2 helpers ----------------
__device__ __forceinline__ ull ffma2(ull a, ull b, ull c) {
  ull d; asm("fma.rn.f32x2 %0, %1, %2, %3;" : "=l"(d) : "l"(a), "l"(b), "l"(c));
  return d;
}
__device__ __forceinline__ ull add2(ull a, ull b) {
  ull d; asm("add.rn.f32x2 %0, %1, %2;" : "=l"(d) : "l"(a), "l"(b));
  return d;
}
__device__ __forceinline__ ull pack2(float lo, float hi) {
  ull r; asm("mov.b64 %0, {%1, %2};" : "=l"(r) : "f"(lo), "f"(hi));
  return r;
}
__device__ __forceinline__ float lo2(ull v) {
  float a; asm("{ .reg .f32 t; mov.b64 {%0, t}, %1; }" : "=f"(a) : "l"(v)); return a;
}
__device__ __forceinline__ float hi2(ull v) {
  float a; asm("{ .reg .f32 t; mov.b64 {t, %0}, %1; }" : "=f"(a) : "l"(v)); return a;
}

// ---------------- threefry2x32 (JAX partitionable path) ----------------
__device__ __forceinline__ unsigned tf_rotl(unsigned x, int r) {
  return (x << r) | (x >> (32 - r));
}
__device__ unsigned threefry_bits32(unsigned k0, unsigned k1, unsigned x0, unsigned x1) {
  unsigned ks0 = k0, ks1 = k1, ks2 = 0x1BD11BDAu ^ k0 ^ k1;
  x0 += ks0; x1 += ks1;
#define TFR(r) { x0 += x1; x1 = tf_rotl(x1, r); x1 ^= x0; }
  TFR(13) TFR(15) TFR(26) TFR(6)   x0 += ks1; x1 += ks2 + 1u;
  TFR(17) TFR(29) TFR(16) TFR(24)  x0 += ks2; x1 += ks0 + 2u;
  TFR(13) TFR(15) TFR(26) TFR(6)   x0 += ks0; x1 += ks1 + 3u;
  TFR(17) TFR(29) TFR(16) TFR(24)  x0 += ks1; x1 += ks2 + 4u;
  TFR(13) TFR(15) TFR(26) TFR(6)   x0 += ks2; x1 += ks0 + 5u;
#undef TFR
  return x0 ^ x1;
}

// ---------------- prep: Wd64 = Wd1 @ (W2 + 0.25 B2@A2) ----------------
__global__ void __launch_bounds__(256) prep_kernel(
    const float* __restrict__ Wd1, const float* __restrict__ W2,
    const float* __restrict__ B2, const float* __restrict__ A2)
{
  const int idx = blockIdx.x*256 + threadIdx.x;   // 0..4095
  const int k = idx >> 6, o = idx & 63;
  const float* wd = Wd1 + k*128;
  float m = 0.f, c0 = 0.f, c1 = 0.f, c2 = 0.f, c3 = 0.f;
#pragma unroll 4
  for (int j = 0; j < 128; j++) {
    float w = wd[j];
    m  = fmaf(w, W2[j*64 + o], m);
    c0 = fmaf(w, B2[j*4 + 0], c0);
    c1 = fmaf(w, B2[j*4 + 1], c1);
    c2 = fmaf(w, B2[j*4 + 2], c2);
    c3 = fmaf(w, B2[j*4 + 3], c3);
  }
  g_Wd64[idx] = m + 0.25f*(c0*A2[o] + c1*A2[64+o] + c2*A2[128+o] + c3*A2[192+o]);
}

// ---------------- encoder ----------------
// smem floats: W1eff[192] | W2eff[128][64] | Wd64[64][64]
#define ENC_SM_W1 0
#define ENC_SM_W2 192
#define ENC_SM_WD (192 + 8192)
#define ENC_SMEM_FLOATS (192 + 8192 + 4096)
#define ENC_SMEM_BYTES  (ENC_SMEM_FLOATS * 4)
#define ENC_PE_BLOCKS 64
#define ENC_PT_BLOCKS 256   // 64 points each, 2 threads/point

// 4 consecutive dots of length 64 (32 packs) against hp
__device__ __forceinline__ float4 dot4(const float* base, const ull* hp) {
  const ulonglong2* w0 = (const ulonglong2*)(base);
  const ulonglong2* w1 = (const ulonglong2*)(base + 64);
  const ulonglong2* w2 = (const ulonglong2*)(base + 128);
  const ulonglong2* w3 = (const ulonglong2*)(base + 192);
  ull a0 = 0ull, a1 = 0ull, a2 = 0ull, a3 = 0ull;
#pragma unroll
  for (int q = 0; q < 16; q++) {
    ulonglong2 v0 = w0[q], v1 = w1[q], v2 = w2[q], v3 = w3[q];
    ull h0 = hp[2*q], h1 = hp[2*q+1];
    a0 = ffma2(v0.x, h0, a0); a0 = ffma2(v0.y, h1, a0);
    a1 = ffma2(v1.x, h0, a1); a1 = ffma2(v1.y, h1, a1);
    a2 = ffma2(v2.x, h0, a2); a2 = ffma2(v2.y, h1, a2);
    a3 = ffma2(v3.x, h0, a3); a3 = ffma2(v3.y, h1, a3);
  }
  float4 r;
  r.x = lo2(a0) + hi2(a0);
  r.y = lo2(a1) + hi2(a1);
  r.z = lo2(a2) + hi2(a2);
  r.w = lo2(a3) + hi2(a3);
  return r;
}

__global__ void __launch_bounds__(128) enc_kernel(
    const float* __restrict__ points, const float* __restrict__ pos_coords,
    const float* __restrict__ W1, const float* __restrict__ A1,
    const float* __restrict__ B1, const float* __restrict__ W2,
    const float* __restrict__ A2, const float* __restrict__ B2,
    const float* __restrict__ Wp, const float* __restrict__ bp,
    const float* __restrict__ Wd1, const float* __restrict__ bd1,
    float* __restrict__ pf_out)
{
  extern __shared__ float sm[];
  const int tid = threadIdx.x;

  if (blockIdx.x < ENC_PE_BLOCKS) {
    // ---- pos_embed + V1 ----
    const int bi = blockIdx.x;
    float* spe = sm;
    const float p0 = pos_coords[bi*3+0], p1 = pos_coords[bi*3+1], p2 = pos_coords[bi*3+2];
    {
      float v = Wp[tid*3+0]*p0 + Wp[tid*3+1]*p1 + Wp[tid*3+2]*p2 + bp[tid];
      spe[tid] = v;
      g_pe[bi*NE + tid] = v;
    }
    __syncthreads();
    if (tid < 64) {
      const float* w = Wd1 + tid*128;
      float acc = 0.0f;
#pragma unroll
      for (int e = 0; e < 128; e++) acc = fmaf(w[e], spe[e], acc);
      g_V1[bi*64 + tid] = acc + bd1[tid];
    }
    return;
  }

  // ---- build folded weights in smem ----
  float* sW1 = sm + ENC_SM_W1;
  float* sW2 = sm + ENC_SM_W2;
  float* sWd = sm + ENC_SM_WD;

  for (int t = tid; t < 192; t += 128) {
    const int o = t / 3, c = t % 3;
    sW1[t] = W1[t] + 0.25f*(B1[o*4+0]*A1[c] + B1[o*4+1]*A1[3+c] +
                            B1[o*4+2]*A1[6+c] + B1[o*4+3]*A1[9+c]);
  }
  for (int t = tid; t < 8192; t += 128) {
    const int j = t >> 6, o = t & 63;
    sW2[t] = W2[t] + 0.25f*(B2[j*4+0]*A2[o] + B2[j*4+1]*A2[64+o] +
                            B2[j*4+2]*A2[128+o] + B2[j*4+3]*A2[192+o]);
  }
  for (int t = tid; t < 4096; t += 128) sWd[t] = g_Wd64[t];
  __syncthreads();

  const int pt   = tid & 63;
  const int half = tid >> 6;
  const int p = (blockIdx.x - ENC_PE_BLOCKS)*64 + pt;
  const float x0 = points[p*3+0], x1 = points[p*3+1], x2 = points[p*3+2];

  // h = relu(W1eff x)
  ull hp[32];
#pragma unroll
  for (int q = 0; q < 32; q++) {
    const float* wa = sW1 + (2*q)*3;
    const float* wb = sW1 + (2*q+1)*3;
    float ha = fmaxf(wa[0]*x0 + wa[1]*x1 + wa[2]*x2, 0.0f);
    float hb = fmaxf(wb[0]*x0 + wb[1]*x1 + wb[2]*x2, 0.0f);
    hp[q] = pack2(ha, hb);
  }

  float* pfrow = pf_out + (size_t)p*128;
  if (half == 0) {
    // pf[0:96]
#pragma unroll 1
    for (int jb = 0; jb < 96; jb += 4) {
      float4 r = dot4(sW2 + jb*64, hp);
      *(float4*)(pfrow + jb) = r;
    }
  } else {
    // pf[96:128] + U[0:64]
#pragma unroll 1
    for (int jb = 96; jb < 128; jb += 4) {
      float4 r = dot4(sW2 + jb*64, hp);
      *(float4*)(pfrow + jb) = r;
    }
    float* urow = g_U + (size_t)p*64;
#pragma unroll 1
    for (int kb = 0; kb < 64; kb += 4) {
      float4 r = dot4(sWd + kb*64, hp);
      *(float4*)(urow + kb) = r;
    }
  }
}

// ---------------- decode ----------------
// grid (NN/128, NB, 4), 8 i's per block.
// MODE 0: write mask bitmaps. MODE 1: write refined logits.
template<int MODE>
__global__ void __launch_bounds__(128) decode_kernel(
    const float* __restrict__ wd2p, const float* __restrict__ bd2p,
    float* __restrict__ out)
{
  __shared__ __align__(16) ull sV[8*32];
  __shared__ __align__(16) ull sW[32];
  const int b = blockIdx.y;
  const int tid = threadIdx.x;
  const int ibase = blockIdx.z * 8;
  const float* Vt = (MODE == 1) ? g_V2 : g_V1;

  for (int t = tid; t < 8*32; t += 128) {
    const int ii = t >> 5, kp = t & 31;
    sV[ii*32 + kp] = ((const ull*)(Vt + (size_t)(b*32 + ibase + ii)*64))[kp];
  }
  if (tid < 32) sW[tid] = pack2(0.5f*wd2p[2*tid], 0.5f*wd2p[2*tid+1]);
  __syncthreads();

  const int n = blockIdx.x*128 + tid;
  ull u2[32];
  const ulonglong2* up = (const ulonglong2*)(g_U + (size_t)(b*NN + n)*64);
#pragma unroll
  for (int q2 = 0; q2 < 16; q2++) {
    ulonglong2 t = up[q2];
    u2[2*q2] = t.x; u2[2*q2+1] = t.y;
  }
  const float bd2 = bd2p[0];
  const ull M = 0x7fffffff7fffffffULL;

#pragma unroll 1
  for (int ii = 0; ii < 8; ii += 2) {
    const ull* va = sV + ii*32;
    const ull* vb = sV + (ii+1)*32;
    ull a0=0ull,a1=0ull,a2=0ull,a3=0ull;
    ull b0=0ull,b1=0ull,b2=0ull,b3=0ull;
#pragma unroll
    for (int q = 0; q < 32; q += 4) {
      { ull u = u2[q],   w = sW[q];
        ull ta = add2(u, va[q]);   ta = add2(ta, ta & M); a0 = ffma2(ta, w, a0);
        ull tb = add2(u, vb[q]);   tb = add2(tb, tb & M); b0 = ffma2(tb, w, b0); }
      { ull u = u2[q+1], w = sW[q+1];
        ull ta = add2(u, va[q+1]); ta = add2(ta, ta & M); a1 = ffma2(ta, w, a1);
        ull tb = add2(u, vb[q+1]); tb = add2(tb, tb & M); b1 = ffma2(tb, w, b1); }
      { ull u = u2[q+2], w = sW[q+2];
        ull ta = add2(u, va[q+2]); ta = add2(ta, ta & M); a2 = ffma2(ta, w, a2);
        ull tb = add2(u, vb[q+2]); tb = add2(tb, tb & M); b2 = ffma2(tb, w, b2); }
      { ull u = u2[q+3], w = sW[q+3];
        ull ta = add2(u, va[q+3]); ta = add2(ta, ta & M); a3 = ffma2(ta, w, a3);
        ull tb = add2(u, vb[q+3]); tb = add2(tb, tb & M); b3 = ffma2(tb, w, b3); }
    }
    float acca = (lo2(a0)+hi2(a0)) + (lo2(a1)+hi2(a1)) +
                 (lo2(a2)+hi2(a2)) + (lo2(a3)+hi2(a3)) + bd2;
    float accb = (lo2(b0)+hi2(b0)) + (lo2(b1)+hi2(b1)) +
                 (lo2(b2)+hi2(b2)) + (lo2(b3)+hi2(b3)) + bd2;
    if (MODE == 1) {
      out[(size_t)(b*32 + ibase + ii)*NN + n]     = acca;
      out[(size_t)(b*32 + ibase + ii + 1)*NN + n] = accb;
    } else {
      unsigned ma = __ballot_sync(0xFFFFFFFFu, acca > 0.0f);
      unsigned mb = __ballot_sync(0xFFFFFFFFu, accb > 0.0f);
      if ((tid & 31) == 0) {
        const int word = n >> 5;
        g_mask[(size_t)(b*32 + ibase + ii)*NWORDS + word]     = ma;
        g_mask[(size_t)(b*32 + ibase + ii + 1)*NWORDS + word] = mb;
      }
    }
  }
}

// ------- intersections + sampling + V2: one 1024-thread block per (b,i) -----
__global__ void __launch_bounds__(1024) samplev2_kernel(
    const float* __restrict__ pos_coords, const float* __restrict__ Wp,
    const float* __restrict__ bp, const float* __restrict__ Wd1,
    const float* __restrict__ bd1)
{
  __shared__ unsigned sMi[NWORDS];
  __shared__ int sInter[32];
  __shared__ int sMsum[32];
  __shared__ float sc[3];
  __shared__ float sd[128];
  const int bi = blockIdx.x, b = bi >> 5, i = bi & 31;
  const int tid = threadIdx.x;
  const int lane = tid & 31, wrp = tid >> 5;   // 32 warps, warp = j

  // cache mask_i
  if (tid < NWORDS) sMi[tid] = g_mask[(size_t)bi*NWORDS + tid];
  __syncthreads();

  // warp wrp handles j = wrp: full-MLP loads, one popc-reduce
  {
    const unsigned* mj = g_mask + (size_t)(b*32 + wrp)*NWORDS;
    int s_ij = 0, s_jj = 0;
#pragma unroll
    for (int c = 0; c < 8; c++) {
      unsigned w = mj[c*32 + lane];
      s_ij += __popc(sMi[c*32 + lane] & w);
      s_jj += __popc(w);
    }
    s_ij = __reduce_add_sync(0xFFFFFFFFu, s_ij);
    s_jj = __reduce_add_sync(0xFFFFFFFFu, s_jj);
    if (lane == 0) { sInter[wrp] = s_ij; sMsum[wrp] = s_jj; }
  }
  __syncthreads();

  if (tid < 32) {
    const int j = tid;
    unsigned comb = 0u;
    if (j != i) {
      float inter = (float)sInter[j];
      float un = (float)sMsum[i] + (float)sMsum[j] - inter;
      float iou = __fdiv_rn(inter, un + 1e-6f);
      if (iou >= 0.1f) {
        unsigned bits = threefry_bits32(0u, 42u, 0u, (unsigned)(bi*32 + j));
        comb = (((bits >> 9) + 1u) << 6) | (unsigned)(31 - j);  // tie -> smaller j
      }
    }
    comb = __reduce_max_sync(0xFFFFFFFFu, comb);
    if (tid == 0) {
      if (comb != 0u) {
        const int j_sel = 31 - (int)(comb & 63u);
        const float* pc = pos_coords + (size_t)(b*32 + j_sel)*3;
        sc[0] = pc[0]; sc[1] = pc[1]; sc[2] = pc[2];
      } else {
        sc[0] = 0.f; sc[1] = 0.f; sc[2] = 0.f;
      }
    }
  }
  __syncthreads();

  if (tid < 128) {
    const int c = tid;
    float ne = Wp[c*3+0]*sc[0] + Wp[c*3+1]*sc[1] + Wp[c*3+2]*sc[2] + bp[c];
    sd[c] = g_pe[bi*NE + c] - ne;
  }
  __syncthreads();

  // V2 GEMV: 2 threads per k (half-rows), shfl combine
  if (tid < 128) {
    const int k = tid >> 1, part = tid & 1;
    const float* w = Wd1 + k*128 + part*64;
    const float* x = sd + part*64;
    float acc = 0.0f;
#pragma unroll
    for (int e = 0; e < 64; e++) acc = fmaf(w[e], x[e], acc);
    float other = __shfl_xor_sync(0xFFFFFFFFu, acc, 1);
    if (part == 0) g_V2[bi*64 + k] = (acc + other) + bd1[k];
  }
}

// ---------------- launch ----------------
extern "C" void kernel_launch(void* const* d_in, const int* in_sizes, int n_in,
                              void* d_out, int out_size)
{
  const float* points = (const float*)d_in[0];
  const float* pos    = (const float*)d_in[1];
  const float* W1     = (const float*)d_in[2];
  const float* A1     = (const float*)d_in[3];
  const float* B1     = (const float*)d_in[4];
  const float* W2     = (const float*)d_in[5];
  const float* A2     = (const float*)d_in[6];
  const float* B2     = (const float*)d_in[7];
  const float* Wp     = (const float*)d_in[8];
  const float* bp     = (const float*)d_in[9];
  const float* Wd1    = (const float*)d_in[10];
  const float* bd1    = (const float*)d_in[11];
  const float* Wd2    = (const float*)d_in[12];
  const float* bd2    = (const float*)d_in[13];

  float* out = (float*)d_out;
  float* refined = out;                       // [2,32,8192]
  float* pf_out  = out + (size_t)NB*NI*NN;    // [2,8192,128]

  cudaFuncSetAttribute(enc_kernel, cudaFuncAttributeMaxDynamicSharedMemorySize,
                       ENC_SMEM_BYTES);

  prep_kernel<<<16, 256>>>(Wd1, W2, B2, A2);
  enc_kernel<<<ENC_PE_BLOCKS + ENC_PT_BLOCKS, 128, ENC_SMEM_BYTES>>>(
      points, pos, W1, A1, B1, W2, A2, B2, Wp, bp, Wd1, bd1, pf_out);
  decode_kernel<0><<<dim3(NN/128, NB, 4), 128>>>(Wd2, bd2, nullptr);
  samplev2_kernel<<<NBI, 1024>>>(pos, Wp, bp, Wd1, bd1);
  decode_kernel<1><<<dim3(NN/128, NB, 4), 128>>>(Wd2, bd2, refined);
}

// round 14
// speedup vs baseline: 1.0345x; 1.0345x over previous
#include <cuda_runtime.h>
#include <cstdint>

typedef unsigned long long ull;

#define NB 2
#define NN 8192
#define NI 32
#define NE 128
#define NP (NB*NN)      // 16384 points
#define NBI (NB*NI)     // 64 (b,i) rows

// ---------------- device scratch ----------------
__device__ float g_U[(size_t)NP*64];    // U = h @ Wd64  (4 MB)
__device__ float g_Wd64[64*64];         // Wd1 @ W2eff   [k][o]
__device__ float g_pe[NBI*NE];          // pos_embed
__device__ float g_V1[NBI*64];          // pe@Wd1^T + bd1
__device__ float g_V2[NBI*64];          // (pe-ne)@Wd1^T + bd1
__device__ int   g_inter[NBI*NI];       // mask intersections (atomic-accumulated)

// ---------------- packed f32x2 helpers ----------------
__device__ __forceinline__ ull ffma2(ull a, ull b, ull c) {
  ull d; asm("fma.rn.f32x2 %0, %1, %2, %3;" : "=l"(d) : "l"(a), "l"(b), "l"(c));
  return d;
}
__device__ __forceinline__ ull add2(ull a, ull b) {
  ull d; asm("add.rn.f32x2 %0, %1, %2;" : "=l"(d) : "l"(a), "l"(b));
  return d;
}
__device__ __forceinline__ ull pack2(float lo, float hi) {
  ull r; asm("mov.b64 %0, {%1, %2};" : "=l"(r) : "f"(lo), "f"(hi));
  return r;
}
__device__ __forceinline__ float lo2(ull v) {
  float a; asm("{ .reg .f32 t; mov.b64 {%0, t}, %1; }" : "=f"(a) : "l"(v)); return a;
}
__device__ __forceinline__ float hi2(ull v) {
  float a; asm("{ .reg .f32 t; mov.b64 {t, %0}, %1; }" : "=f"(a) : "l"(v)); return a;
}

// ---------------- threefry2x32 (JAX partitionable path) ----------------
__device__ __forceinline__ unsigned tf_rotl(unsigned x, int r) {
  return (x << r) | (x >> (32 - r));
}
__device__ unsigned threefry_bits32(unsigned k0, unsigned k1, unsigned x0, unsigned x1) {
  unsigned ks0 = k0, ks1 = k1, ks2 = 0x1BD11BDAu ^ k0 ^ k1;
  x0 += ks0; x1 += ks1;
#define TFR(r) { x0 += x1; x1 = tf_rotl(x1, r); x1 ^= x0; }
  TFR(13) TFR(15) TFR(26) TFR(6)   x0 += ks1; x1 += ks2 + 1u;
  TFR(17) TFR(29) TFR(16) TFR(24)  x0 += ks2; x1 += ks0 + 2u;
  TFR(13) TFR(15) TFR(26) TFR(6)   x0 += ks0; x1 += ks1 + 3u;
  TFR(17) TFR(29) TFR(16) TFR(24)  x0 += ks1; x1 += ks2 + 4u;
  TFR(13) TFR(15) TFR(26) TFR(6)   x0 += ks2; x1 += ks0 + 5u;
#undef TFR
  return x0 ^ x1;
}

// ---------------- prep: Wd64 = Wd1 @ (W2 + 0.25 B2@A2) ----------------
__global__ void __launch_bounds__(256) prep_kernel(
    const float* __restrict__ Wd1, const float* __restrict__ W2,
    const float* __restrict__ B2, const float* __restrict__ A2)
{
  const int idx = blockIdx.x*256 + threadIdx.x;   // 0..4095
  const int k = idx >> 6, o = idx & 63;
  const float* wd = Wd1 + k*128;
  float m = 0.f, c0 = 0.f, c1 = 0.f, c2 = 0.f, c3 = 0.f;
#pragma unroll 4
  for (int j = 0; j < 128; j++) {
    float w = wd[j];
    m  = fmaf(w, W2[j*64 + o], m);
    c0 = fmaf(w, B2[j*4 + 0], c0);
    c1 = fmaf(w, B2[j*4 + 1], c1);
    c2 = fmaf(w, B2[j*4 + 2], c2);
    c3 = fmaf(w, B2[j*4 + 3], c3);
  }
  g_Wd64[idx] = m + 0.25f*(c0*A2[o] + c1*A2[64+o] + c2*A2[128+o] + c3*A2[192+o]);
}

// ---------------- encoder ----------------
// smem floats: W1eff[192] | W2eff[128][64] | Wd64[64][64]
#define ENC_SM_W1 0
#define ENC_SM_W2 192
#define ENC_SM_WD (192 + 8192)
#define ENC_SMEM_FLOATS (192 + 8192 + 4096)
#define ENC_SMEM_BYTES  (ENC_SMEM_FLOATS * 4)
#define ENC_PE_BLOCKS 64
#define ENC_PT_BLOCKS 256   // 64 points each, 2 threads/point

// 4 consecutive dots of length 64 (32 packs) against hp
__device__ __forceinline__ float4 dot4(const float* base, const ull* hp) {
  const ulonglong2* w0 = (const ulonglong2*)(base);
  const ulonglong2* w1 = (const ulonglong2*)(base + 64);
  const ulonglong2* w2 = (const ulonglong2*)(base + 128);
  const ulonglong2* w3 = (const ulonglong2*)(base + 192);
  ull a0 = 0ull, a1 = 0ull, a2 = 0ull, a3 = 0ull;
#pragma unroll
  for (int q = 0; q < 16; q++) {
    ulonglong2 v0 = w0[q], v1 = w1[q], v2 = w2[q], v3 = w3[q];
    ull h0 = hp[2*q], h1 = hp[2*q+1];
    a0 = ffma2(v0.x, h0, a0); a0 = ffma2(v0.y, h1, a0);
    a1 = ffma2(v1.x, h0, a1); a1 = ffma2(v1.y, h1, a1);
    a2 = ffma2(v2.x, h0, a2); a2 = ffma2(v2.y, h1, a2);
    a3 = ffma2(v3.x, h0, a3); a3 = ffma2(v3.y, h1, a3);
  }
  float4 r;
  r.x = lo2(a0) + hi2(a0);
  r.y = lo2(a1) + hi2(a1);
  r.z = lo2(a2) + hi2(a2);
  r.w = lo2(a3) + hi2(a3);
  return r;
}

__global__ void __launch_bounds__(128) enc_kernel(
    const float* __restrict__ points, const float* __restrict__ pos_coords,
    const float* __restrict__ W1, const float* __restrict__ A1,
    const float* __restrict__ B1, const float* __restrict__ W2,
    const float* __restrict__ A2, const float* __restrict__ B2,
    const float* __restrict__ Wp, const float* __restrict__ bp,
    const float* __restrict__ Wd1, const float* __restrict__ bd1,
    float* __restrict__ pf_out)
{
  extern __shared__ float sm[];
  const int tid = threadIdx.x;

  if (blockIdx.x < ENC_PE_BLOCKS) {
    // ---- pos_embed + V1 + zero g_inter ----
    const int bi = blockIdx.x;
    float* spe = sm;
    if (tid < 32) g_inter[bi*32 + tid] = 0;
    const float p0 = pos_coords[bi*3+0], p1 = pos_coords[bi*3+1], p2 = pos_coords[bi*3+2];
    {
      float v = Wp[tid*3+0]*p0 + Wp[tid*3+1]*p1 + Wp[tid*3+2]*p2 + bp[tid];
      spe[tid] = v;
      g_pe[bi*NE + tid] = v;
    }
    __syncthreads();
    if (tid < 64) {
      const float* w = Wd1 + tid*128;
      float acc = 0.0f;
#pragma unroll
      for (int e = 0; e < 128; e++) acc = fmaf(w[e], spe[e], acc);
      g_V1[bi*64 + tid] = acc + bd1[tid];
    }
    return;
  }

  // ---- build folded weights in smem ----
  float* sW1 = sm + ENC_SM_W1;
  float* sW2 = sm + ENC_SM_W2;
  float* sWd = sm + ENC_SM_WD;

  for (int t = tid; t < 192; t += 128) {
    const int o = t / 3, c = t % 3;
    sW1[t] = W1[t] + 0.25f*(B1[o*4+0]*A1[c] + B1[o*4+1]*A1[3+c] +
                            B1[o*4+2]*A1[6+c] + B1[o*4+3]*A1[9+c]);
  }
  for (int t = tid; t < 8192; t += 128) {
    const int j = t >> 6, o = t & 63;
    sW2[t] = W2[t] + 0.25f*(B2[j*4+0]*A2[o] + B2[j*4+1]*A2[64+o] +
                            B2[j*4+2]*A2[128+o] + B2[j*4+3]*A2[192+o]);
  }
  for (int t = tid; t < 4096; t += 128) sWd[t] = g_Wd64[t];
  __syncthreads();

  const int pt   = tid & 63;
  const int half = tid >> 6;
  const int p = (blockIdx.x - ENC_PE_BLOCKS)*64 + pt;
  const float x0 = points[p*3+0], x1 = points[p*3+1], x2 = points[p*3+2];

  // h = relu(W1eff x)
  ull hp[32];
#pragma unroll
  for (int q = 0; q < 32; q++) {
    const float* wa = sW1 + (2*q)*3;
    const float* wb = sW1 + (2*q+1)*3;
    float ha = fmaxf(wa[0]*x0 + wa[1]*x1 + wa[2]*x2, 0.0f);
    float hb = fmaxf(wb[0]*x0 + wb[1]*x1 + wb[2]*x2, 0.0f);
    hp[q] = pack2(ha, hb);
  }

  float* pfrow = pf_out + (size_t)p*128;
  if (half == 0) {
    // pf[0:96]
#pragma unroll 1
    for (int jb = 0; jb < 96; jb += 4) {
      float4 r = dot4(sW2 + jb*64, hp);
      *(float4*)(pfrow + jb) = r;
    }
  } else {
    // pf[96:128] + U[0:64]
#pragma unroll 1
    for (int jb = 96; jb < 128; jb += 4) {
      float4 r = dot4(sW2 + jb*64, hp);
      *(float4*)(pfrow + jb) = r;
    }
    float* urow = g_U + (size_t)p*64;
#pragma unroll 1
    for (int kb = 0; kb < 64; kb += 4) {
      float4 r = dot4(sWd + kb*64, hp);
      *(float4*)(urow + kb) = r;
    }
  }
}

// ---------------- decode ----------------
// MODE 0: grid (NN/128, NB): all 32 i per block; masks -> in-block popc
//         intersections -> atomicAdd(g_inter).
// MODE 1: grid (NN/128, NB, 4): 8 i per block; write refined logits.
template<int MODE>
__global__ void __launch_bounds__(128) decode_kernel(
    const float* __restrict__ wd2p, const float* __restrict__ bd2p,
    float* __restrict__ out)
{
  __shared__ __align__(16) ull sV[32*32];
  __shared__ __align__(16) ull sW[32];
  __shared__ unsigned sB[32*4];
  const int b = blockIdx.y;
  const int tid = threadIdx.x;
  const int ibase  = (MODE == 1) ? blockIdx.z * 8 : 0;
  const int icount = (MODE == 1) ? 8 : 32;
  const float* Vt = (MODE == 1) ? g_V2 : g_V1;

  for (int t = tid; t < icount*32; t += 128) {
    const int ii = t >> 5, kp = t & 31;
    sV[ii*32 + kp] = ((const ull*)(Vt + (size_t)(b*32 + ibase + ii)*64))[kp];
  }
  if (tid < 32) sW[tid] = pack2(0.5f*wd2p[2*tid], 0.5f*wd2p[2*tid+1]);
  __syncthreads();

  const int n = blockIdx.x*128 + tid;
  ull u2[32];
  const ulonglong2* up = (const ulonglong2*)(g_U + (size_t)(b*NN + n)*64);
#pragma unroll
  for (int q2 = 0; q2 < 16; q2++) {
    ulonglong2 t = up[q2];
    u2[2*q2] = t.x; u2[2*q2+1] = t.y;
  }
  const float bd2 = bd2p[0];
  const ull M = 0x7fffffff7fffffffULL;

#pragma unroll 1
  for (int ii = 0; ii < icount; ii += 2) {
    const ull* va = sV + ii*32;
    const ull* vb = sV + (ii+1)*32;
    ull a0=0ull,a1=0ull,a2=0ull,a3=0ull;
    ull b0=0ull,b1=0ull,b2=0ull,b3=0ull;
#pragma unroll
    for (int q = 0; q < 32; q += 4) {
      { ull u = u2[q],   w = sW[q];
        ull ta = add2(u, va[q]);   ta = add2(ta, ta & M); a0 = ffma2(ta, w, a0);
        ull tb = add2(u, vb[q]);   tb = add2(tb, tb & M); b0 = ffma2(tb, w, b0); }
      { ull u = u2[q+1], w = sW[q+1];
        ull ta = add2(u, va[q+1]); ta = add2(ta, ta & M); a1 = ffma2(ta, w, a1);
        ull tb = add2(u, vb[q+1]); tb = add2(tb, tb & M); b1 = ffma2(tb, w, b1); }
      { ull u = u2[q+2], w = sW[q+2];
        ull ta = add2(u, va[q+2]); ta = add2(ta, ta & M); a2 = ffma2(ta, w, a2);
        ull tb = add2(u, vb[q+2]); tb = add2(tb, tb & M); b2 = ffma2(tb, w, b2); }
      { ull u = u2[q+3], w = sW[q+3];
        ull ta = add2(u, va[q+3]); ta = add2(ta, ta & M); a3 = ffma2(ta, w, a3);
        ull tb = add2(u, vb[q+3]); tb = add2(tb, tb & M); b3 = ffma2(tb, w, b3); }
    }
    float acca = (lo2(a0)+hi2(a0)) + (lo2(a1)+hi2(a1)) +
                 (lo2(a2)+hi2(a2)) + (lo2(a3)+hi2(a3)) + bd2;
    float accb = (lo2(b0)+hi2(b0)) + (lo2(b1)+hi2(b1)) +
                 (lo2(b2)+hi2(b2)) + (lo2(b3)+hi2(b3)) + bd2;
    if (MODE == 1) {
      out[(size_t)(b*32 + ibase + ii)*NN + n]     = acca;
      out[(size_t)(b*32 + ibase + ii + 1)*NN + n] = accb;
    } else {
      unsigned ma = __ballot_sync(0xFFFFFFFFu, acca > 0.0f);
      unsigned mb = __ballot_sync(0xFFFFFFFFu, accb > 0.0f);
      if ((tid & 31) == 0) {
        sB[ii*4 + (tid >> 5)]     = ma;
        sB[(ii+1)*4 + (tid >> 5)] = mb;
      }
    }
  }

  if (MODE == 0) {
    __syncthreads();
    // 1024 (i,j) pairs; diagonal gives m_sum
#pragma unroll
    for (int pr = 0; pr < 8; pr++) {
      const int pair = pr*128 + tid;
      const int i = pair >> 5, j = pair & 31;
      int v = 0;
#pragma unroll
      for (int c = 0; c < 4; c++) v += __popc(sB[i*4 + c] & sB[j*4 + c]);
      atomicAdd(&g_inter[(b*32 + i)*32 + j], v);
    }
  }
}

// ---------------- sampling + V2 (one 128-thread block per (b,i)) ----------
__global__ void __launch_bounds__(128) samplev2_kernel(
    const float* __restrict__ pos_coords, const float* __restrict__ Wp,
    const float* __restrict__ bp, const float* __restrict__ Wd1,
    const float* __restrict__ bd1)
{
  __shared__ float sdiag[32];
  __shared__ float srow[32];
  __shared__ float sc[3];
  __shared__ float sd[128];
  const int bi = blockIdx.x, b = bi >> 5, i = bi & 31;
  const int tid = threadIdx.x;

  if (tid < 32) {
    srow[tid]  = (float)g_inter[bi*32 + tid];
    sdiag[tid] = (float)g_inter[(b*32 + tid)*32 + tid];
  }
  __syncthreads();

  if (tid < 32) {
    const int j = tid;
    unsigned comb = 0u;
    if (j != i) {
      float inter = srow[j];
      float un = sdiag[i] + sdiag[j] - inter;
      float iou = __fdiv_rn(inter, un + 1e-6f);
      if (iou >= 0.1f) {
        unsigned bits = threefry_bits32(0u, 42u, 0u, (unsigned)(bi*32 + j));
        comb = (((bits >> 9) + 1u) << 6) | (unsigned)(31 - j);  // tie -> smaller j
      }
    }
    comb = __reduce_max_sync(0xFFFFFFFFu, comb);
    if (tid == 0) {
      if (comb != 0u) {
        const int j_sel = 31 - (int)(comb & 63u);
        const float* pc = pos_coords + (size_t)(b*32 + j_sel)*3;
        sc[0] = pc[0]; sc[1] = pc[1]; sc[2] = pc[2];
      } else {
        sc[0] = 0.f; sc[1] = 0.f; sc[2] = 0.f;
      }
    }
  }
  __syncthreads();

  {
    const int c = tid;
    float ne = Wp[c*3+0]*sc[0] + Wp[c*3+1]*sc[1] + Wp[c*3+2]*sc[2] + bp[c];
    sd[c] = g_pe[bi*NE + c] - ne;
  }
  __syncthreads();

  if (tid < 64) {
    const float* w = Wd1 + tid*128;
    float acc = 0.0f;
#pragma unroll
    for (int e = 0; e < 128; e++) acc = fmaf(w[e], sd[e], acc);
    g_V2[bi*64 + tid] = acc + bd1[tid];
  }
}

// ---------------- launch ----------------
extern "C" void kernel_launch(void* const* d_in, const int* in_sizes, int n_in,
                              void* d_out, int out_size)
{
  const float* points = (const float*)d_in[0];
  const float* pos    = (const float*)d_in[1];
  const float* W1     = (const float*)d_in[2];
  const float* A1     = (const float*)d_in[3];
  const float* B1     = (const float*)d_in[4];
  const float* W2     = (const float*)d_in[5];
  const float* A2     = (const float*)d_in[6];
  const float* B2     = (const float*)d_in[7];
  const float* Wp     = (const float*)d_in[8];
  const float* bp     = (const float*)d_in[9];
  const float* Wd1    = (const float*)d_in[10];
  const float* bd1    = (const float*)d_in[11];
  const float* Wd2    = (const float*)d_in[12];
  const float* bd2    = (const float*)d_in[13];

  float* out = (float*)d_out;
  float* refined = out;                       // [2,32,8192]
  float* pf_out  = out + (size_t)NB*NI*NN;    // [2,8192,128]

  cudaFuncSetAttribute(enc_kernel, cudaFuncAttributeMaxDynamicSharedMemorySize,
                       ENC_SMEM_BYTES);

  prep_kernel<<<16, 256>>>(Wd1, W2, B2, A2);
  enc_kernel<<<ENC_PE_BLOCKS + ENC_PT_BLOCKS, 128, ENC_SMEM_BYTES>>>(
      points, pos, W1, A1, B1, W2, A2, B2, Wp, bp, Wd1, bd1, pf_out);
  decode_kernel<0><<<dim3(NN/128, NB), 128>>>(Wd2, bd2, nullptr);
  samplev2_kernel<<<NBI, 128>>>(pos, Wp, bp, Wd1, bd1);
  decode_kernel<1><<<dim3(NN/128, NB, 4), 128>>>(Wd2, bd2, refined);
}